// round 14
// baseline (speedup 1.0000x reference)
#include <cuda_runtime.h>
#include <math.h>
#include <cstdint>

// Fixed shape: query_len = key_len = 2048, 8 fp32 channels, TRUNC = 200.
#define QL 2048
#define KL 2048
#define NT 201              // distinct T values 0..200 (T>200 -> T=0 vector)
#define THREADS 256
#define HALF 1024           // CTA = half-row (1024 px = 32 KB out)
#define CPIX 512            // const staging buffer: 512 px = 16 KB
#define BAND_MAX 416        // band within a half-row <= 401 px

__device__ __forceinline__ uint32_t smem_u32(const void* p) {
    uint32_t a;
    asm("{ .reg .u64 t; cvta.to.shared.u64 t, %1; cvt.u32.u64 %0, t; }"
        : "=r"(a) : "l"(p));
    return a;
}

__device__ __forceinline__ void bulk_s2g(float4* g, uint32_t s, int bytes) {
    asm volatile("cp.async.bulk.global.shared::cta.bulk_group [%0], [%1], %2;"
                 :: "l"(g), "r"(s), "r"(bytes) : "memory");
}

// Warp-specialized prologue (R13 + two latency cuts):
//  - warp 0 alone fills the const buffer and posts the const copies after a
//    __syncwarp -- the first copy no longer waits on a block barrier;
//  - warps 1-7 build the LUT concurrently (tid-32 -> 201 entries), using
//    fast __powf (exp2/log2 path, rel err ~5e-5 << 1e-3 tolerance);
//    accurate sincosf kept (args up to ~400 rad, __sinf unsafe there).
__global__ __launch_bounds__(THREADS) void fill_half4_kernel(
    const float* __restrict__ eta, const float* __restrict__ nu,
    const float* __restrict__ theta, float4* __restrict__ out)
{
    __shared__ __align__(16) float4 cbuf[CPIX * 2];      // 16 KB, constant
    __shared__ __align__(16) float4 bbuf[BAND_MAX * 2];  // 13 KB, band
    __shared__ __align__(16) float4 lut[2 * NT];         // 6.4 KB

    const int tid   = threadIdx.x;
    const int i     = blockIdx.x >> 1;              // row
    const int pbase = (blockIdx.x & 1) * HALF;      // half offset in row

    const float4 farA = make_float4(1.f, 1.f, 0.f, 0.f);
    const float4 farB = make_float4(1.f, 1.f, 1.f, 0.f);
    float4* gp = out + ((size_t)i * KL + pbase) * 2;

    // Band |i-j| <= 200 clamped to this half-row [pbase, pbase+HALF).
    int lo = i - 200;  if (lo < pbase) lo = pbase;
    int hi = i + 200;  if (hi > pbase + HALF - 1) hi = pbase + HALF - 1;
    const bool has_band = (lo <= hi);               // uniform per block

    if (tid < 32) {
        // ---- warp 0: const buffer fill + post const copies ----
#pragma unroll
        for (int k = 0; k < (CPIX * 2) / 32; k++) {
            int f = k * 32 + tid;
            cbuf[f] = (f & 1) ? farB : farA;
        }
        __syncwarp();
        if (tid == 0) {
            asm volatile("fence.proxy.async.shared::cta;" ::: "memory");
            const uint32_t cb = smem_u32(cbuf);
            if (!has_band) {
                bulk_s2g(gp,            cb, CPIX * 32);
                bulk_s2g(gp + 2 * CPIX, cb, CPIX * 32);
            } else {
                int rem = lo - pbase, off = 0;        // left const segment
                while (rem > 0) {
                    int n = (rem < CPIX) ? rem : CPIX;
                    bulk_s2g(gp + 2 * off, cb, n * 32);
                    off += n; rem -= n;
                }
                rem = (pbase + HALF - 1) - hi;        // right const segment
                off = hi + 1 - pbase;
                while (rem > 0) {
                    int n = (rem < CPIX) ? rem : CPIX;
                    bulk_s2g(gp + 2 * off, cb, n * 32);
                    off += n; rem -= n;
                }
            }
            asm volatile("cp.async.bulk.commit_group;" ::: "memory");
        }
    } else if (has_band && tid - 32 < NT) {
        // ---- warps 1-7: LUT build, concurrent with warp 0's prologue ----
        const int t = tid - 32;
        float lambda = tanhf(eta[0]);
        float gamma  = 1.0f / (1.0f + expf(-nu[0]));
        float th     = theta[0];
        float T      = (float)t;

        float gT = __powf(gamma, T);
        float s, c;  sincosf(T * th, &s, &c);
        float v0 = gT * c;            // ch0, ch1
        float v2 = gT * s;            // ch2, ch3

        float L2d = (t % 2  == 0) ? T * 0.5f    : 0.0f;
        float L4d = (t % 4  == 0) ? T * 0.25f   : 0.0f;
        float L8d = (t % 8  == 0) ? T * 0.125f  : 0.0f;
        float L16 = (t % 16 == 0) ? T * 0.0625f : 0.0f;

        float v4 = __powf(lambda, L2d);                 // ch4
        float v5 = __powf(lambda, L4d);                 // ch5
        float s8, c8;   sincosf(L8d * th, &s8, &c8);
        float s16, c16; sincosf(L16 * th, &s16, &c16);
        float v6 = __powf(gamma, L8d) * c8;             // ch6
        float v7 = __powf(gamma, L16) * s16;            // ch7

        lut[2 * t]     = make_float4(v0, v0, v2, v2);
        lut[2 * t + 1] = make_float4(v4, v5, v6, v7);
    }

    if (has_band) {
        __syncthreads();    // lut visible to all

        // ---- band fill (<= 401 px; T <= 200 by construction) ----
        const int npix = hi - lo + 1;
        for (int k = tid; k < npix; k += THREADS) {
            int j = lo + k;
            int T = i - j;  T = (T < 0) ? -T : T;
            bbuf[2 * k]     = lut[2 * T];
            bbuf[2 * k + 1] = lut[2 * T + 1];
        }
        __syncthreads();

        // ---- band copy ----
        if (tid == 0) {
            asm volatile("fence.proxy.async.shared::cta;" ::: "memory");
            bulk_s2g(gp + 2 * (lo - pbase), smem_u32(bbuf), npix * 32);
            asm volatile("cp.async.bulk.commit_group;" ::: "memory");
        }
    }

    // Exit after SMEM-read completion only; global visibility is covered
    // by kernel-completion semantics.
    if (tid == 0)
        asm volatile("cp.async.bulk.wait_group.read 0;" ::: "memory");
}

extern "C" void kernel_launch(void* const* d_in, const int* in_sizes, int n_in,
                              void* d_out, int out_size) {
    const float* eta   = (const float*)d_in[0];
    const float* nu    = (const float*)d_in[1];
    const float* theta = (const float*)d_in[2];

    fill_half4_kernel<<<QL * 2, THREADS>>>(eta, nu, theta, (float4*)d_out);
}